// round 8
// baseline (speedup 1.0000x reference)
#include <cuda_runtime.h>
#include <cstdint>

// RoiPoolingConv: img [1,256,256,512] f32 (NHWC), rois [1,1024,4] i32 (x1,y1,x2,y2)
// out [1,1024,7,7,512] f32 — TF1-legacy bilinear crop-resize to 7x7.
//
// R7: R4 structure (block per (roi,py) row, grid 7168, 128 thr, 64 regs) with
// inverted cache policy:
//   - image loads:  __ldcs (evict-first; reuse window is microseconds, lines
//                   are dead afterwards -> preferred eviction victims)
//   - output stores: plain write-back (normal retention). Output is 103 MB vs
//                   126 MB L2; across graph replays the same lines are
//                   overwritten in L2 and need never reach DRAM.
// Goal: cut steady-state per-replay DRAM traffic from 234 MB toward ~131 MB.

#define POOL 7
#define IMG_W 256
#define IMG_C 512
#define NVEC (IMG_C / 4)   // 128 float4 per pixel

__global__ __launch_bounds__(NVEC, 8)
void roi_pool_row_kernel(const float* __restrict__ img,
                         const int*   __restrict__ rois,
                         float*       __restrict__ out)
{
    const int py  = blockIdx.x;          // 0..6
    const int roi = blockIdx.y;          // 0..1023

    // ROI descriptor: 16B aligned, uniform across block
    const int4 r = __ldg(reinterpret_cast<const int4*>(rois) + roi);
    const int x1 = r.x, y1 = r.y, x2 = r.z, y2 = r.w;

    const float h = (float)(y2 - y1);
    const float w = (float)(x2 - x1);

    // Reference op order: (h / P) first, then scale by index.
    const float ys = (float)py * (h / 7.0f);
    const int   y0 = (int)floorf(ys);
    const int ymax = max(y2 - y1 - 1, 0);
    const int xmax = max(x2 - x1 - 1, 0);
    const int  y1i = min(y0 + 1, ymax);
    const float wy = ys - (float)y0;

    const int row0 = y1 + y0;
    const int row1 = y1 + y1i;

    const float4* __restrict__ base = reinterpret_cast<const float4*>(img);
    const int c = threadIdx.x;           // 0..127 (float4 index within channels)

    const float4* __restrict__ b0 = base + (size_t)row0 * IMG_W * NVEC + c;
    const float4* __restrict__ b1 = base + (size_t)row1 * IMG_W * NVEC + c;

    float4* __restrict__ orow = reinterpret_cast<float4*>(out)
                              + ((size_t)roi * (POOL * POOL) + (size_t)py * POOL) * NVEC + c;

    const float w_over_7 = w / 7.0f;

#pragma unroll
    for (int px = 0; px < POOL; ++px) {
        const float xs = (float)px * w_over_7;
        const int   x0 = (int)floorf(xs);
        const int  x1i = min(x0 + 1, xmax);
        const float wx = xs - (float)x0;

        const float w00 = (1.0f - wy) * (1.0f - wx);
        const float w01 = (1.0f - wy) * wx;
        const float w10 = wy * (1.0f - wx);
        const float w11 = wy * wx;

        const int col0 = x1 + x0;
        const int col1 = x1 + x1i;

        // Streaming (evict-first) reads: short reuse window only.
        const float4 v00 = __ldcs(b0 + (size_t)col0 * NVEC);
        const float4 v01 = __ldcs(b0 + (size_t)col1 * NVEC);
        const float4 v10 = __ldcs(b1 + (size_t)col0 * NVEC);
        const float4 v11 = __ldcs(b1 + (size_t)col1 * NVEC);

        float4 o;
        o.x = fmaf(v00.x, w00, fmaf(v01.x, w01, fmaf(v10.x, w10, v11.x * w11)));
        o.y = fmaf(v00.y, w00, fmaf(v01.y, w01, fmaf(v10.y, w10, v11.y * w11)));
        o.z = fmaf(v00.z, w00, fmaf(v01.z, w01, fmaf(v10.z, w10, v11.z * w11)));
        o.w = fmaf(v00.w, w00, fmaf(v01.w, w01, fmaf(v10.w, w10, v11.w * w11)));

        // Write-back store: let dirty output lines persist in L2 across
        // graph replays (output 103 MB < L2 126 MB).
        orow[(size_t)px * NVEC] = o;
    }
}

extern "C" void kernel_launch(void* const* d_in, const int* in_sizes, int n_in,
                              void* d_out, int out_size)
{
    const float* img  = (const float*)d_in[0];   // [1,256,256,512] f32
    const int*   rois = (const int*)d_in[1];     // [1,1024,4] i32
    float*       out  = (float*)d_out;           // [1,1024,7,7,512] f32

    dim3 grid(POOL, 1024);
    roi_pool_row_kernel<<<grid, NVEC>>>(img, rois, out);
}

// round 9
// speedup vs baseline: 1.7164x; 1.7164x over previous
#include <cuda_runtime.h>
#include <cstdint>

// RoiPoolingConv: img [1,256,256,512] f32 (NHWC), rois [1,1024,4] i32 (x1,y1,x2,y2)
// out [1,1024,7,7,512] f32 — TF1-legacy bilinear crop-resize to 7x7.
//
// R8: R4 skeleton (block per (roi,py) row, grid 7168, 128 thr, full unroll,
// __ldg reads + __stcs stores) PLUS zero-weight tap DEDUP: when wy==0
// (py==0 or h%7==0) point row1 at row0; when wx==0 (px==0 or w%7==0) point
// col1 at col0. Duplicate loads are L1 broadcasts (no extra DRAM sectors),
// weights are exactly 0 so results are bit-identical, and the unique DRAM
// read footprint shrinks by the never-otherwise-sampled rows/columns.

#define POOL 7
#define IMG_W 256
#define IMG_C 512
#define NVEC (IMG_C / 4)   // 128 float4 per pixel

__global__ __launch_bounds__(NVEC, 8)
void roi_pool_row_kernel(const float* __restrict__ img,
                         const int*   __restrict__ rois,
                         float*       __restrict__ out)
{
    const int py  = blockIdx.x;          // 0..6
    const int roi = blockIdx.y;          // 0..1023

    // ROI descriptor: 16B aligned, uniform across block
    const int4 r = __ldg(reinterpret_cast<const int4*>(rois) + roi);
    const int x1 = r.x, y1 = r.y, x2 = r.z, y2 = r.w;

    const int hi = y2 - y1;
    const int wi = x2 - x1;
    const float h = (float)hi;
    const float w = (float)wi;

    // Reference op order: (h / P) first, then scale by index.
    const float ys = (float)py * (h / 7.0f);
    const int   y0 = (int)floorf(ys);
    const int ymax = max(hi - 1, 0);
    const int xmax = max(wi - 1, 0);
    const int  y1i = min(y0 + 1, ymax);
    const float wy = ys - (float)y0;

    // wy == 0 exactly iff py==0 or h % 7 == 0 (7 prime, exact fp division
    // for multiples). Then w10 = w11 = 0 -> row1's value is irrelevant:
    // alias it to row0 so the loads are L1-broadcast duplicates instead of
    // unique DRAM rows.
    const bool wy_zero = (py == 0) || (hi % 7 == 0);
    const int row0 = y1 + y0;
    const int row1 = wy_zero ? row0 : (y1 + y1i);

    // Same logic for columns: wx == 0 for ALL px>0 iff w % 7 == 0.
    const bool wx_zero_all = (wi % 7 == 0);

    const float4* __restrict__ base = reinterpret_cast<const float4*>(img);
    const int c = threadIdx.x;           // 0..127 (float4 index within channels)

    const float4* __restrict__ b0 = base + (size_t)row0 * IMG_W * NVEC + c;
    const float4* __restrict__ b1 = base + (size_t)row1 * IMG_W * NVEC + c;

    float4* __restrict__ orow = reinterpret_cast<float4*>(out)
                              + ((size_t)roi * (POOL * POOL) + (size_t)py * POOL) * NVEC + c;

    const float w_over_7 = w / 7.0f;

#pragma unroll
    for (int px = 0; px < POOL; ++px) {
        const float xs = (float)px * w_over_7;
        const int   x0 = (int)floorf(xs);
        const int  x1i = min(x0 + 1, xmax);
        const float wx = xs - (float)x0;

        const float w00 = (1.0f - wy) * (1.0f - wx);
        const float w01 = (1.0f - wy) * wx;
        const float w10 = wy * (1.0f - wx);
        const float w11 = wy * wx;

        const int col0 = x1 + x0;
        // px==0 folds at compile time (wx always 0 there).
        const int col1 = (px == 0 || wx_zero_all) ? col0 : (x1 + x1i);

        const float4 v00 = __ldg(b0 + (size_t)col0 * NVEC);
        const float4 v01 = __ldg(b0 + (size_t)col1 * NVEC);
        const float4 v10 = __ldg(b1 + (size_t)col0 * NVEC);
        const float4 v11 = __ldg(b1 + (size_t)col1 * NVEC);

        float4 o;
        o.x = fmaf(v00.x, w00, fmaf(v01.x, w01, fmaf(v10.x, w10, v11.x * w11)));
        o.y = fmaf(v00.y, w00, fmaf(v01.y, w01, fmaf(v10.y, w10, v11.y * w11)));
        o.z = fmaf(v00.z, w00, fmaf(v01.z, w01, fmaf(v10.z, w10, v11.z * w11)));
        o.w = fmaf(v00.w, w00, fmaf(v01.w, w01, fmaf(v10.w, w10, v11.w * w11)));

        __stcs(orow + (size_t)px * NVEC, o);
    }
}

extern "C" void kernel_launch(void* const* d_in, const int* in_sizes, int n_in,
                              void* d_out, int out_size)
{
    const float* img  = (const float*)d_in[0];   // [1,256,256,512] f32
    const int*   rois = (const int*)d_in[1];     // [1,1024,4] i32
    float*       out  = (float*)d_out;           // [1,1024,7,7,512] f32

    dim3 grid(POOL, 1024);
    roi_pool_row_kernel<<<grid, NVEC>>>(img, rois, out);
}